// round 3
// baseline (speedup 1.0000x reference)
#include <cuda_runtime.h>
#include <cuda_bf16.h>

// Problem constants: B=8, C=64, H=W=128, G=2, D=32, K=9, OS=2.0
#define PB 16384
#define NB 8
#define NROWS (NB * PB)

__device__ float g_value[NB * PB * 64];   // (b,p,64)
__device__ float g_om[NB * PB * 54];      // (b,p,54)

// ---------------------------------------------------------------------------
// K1: value projection. 128 rows x 64 j tile, 256 thr, micro 8 rows x 4 j.
// As column-swizzled (XOR 16 on col when (row>>3)&1) -> conflict-free
// two-row-group broadcasts. smem = 32KB + 16KB = 48KB.
// ---------------------------------------------------------------------------
__global__ void __launch_bounds__(256) k1_valproj(const float* __restrict__ x,
                                                  const float* __restrict__ vp_w,
                                                  const float* __restrict__ vp_b) {
    __shared__ float As[128 * 64];   // As[r*64 + (c ^ swz(r))]
    __shared__ float Wt[64 * 64];    // Wt[c*64 + j]
    int t = threadIdx.x;
    for (int i = t; i < 4096; i += 256) Wt[(i & 63) * 64 + (i >> 6)] = vp_w[i];

    size_t row0 = (size_t)blockIdx.x * 128;
    const float4* xv = (const float4*)(x + row0 * 64);
    for (int i = t; i < 2048; i += 256) {
        int r = i >> 4;
        int c4 = (i & 15) * 4;
        int s = ((r >> 3) & 1) << 4;
        *(float4*)&As[r * 64 + (c4 ^ s)] = xv[i];
    }
    __syncthreads();

    int j0 = (t & 15) * 4;
    int r0 = (t >> 4) * 8;                 // rows r0..r0+7 share swizzle
    int s  = ((t >> 4) & 1) << 4;
    float acc[8][4] = {};

    const float* ap = As + r0 * 64;
    const float* wp = Wt + j0;
#pragma unroll 4
    for (int c = 0; c < 64; c++) {
        int cc = c ^ s;
        float4 b = *(const float4*)(wp + c * 64);
        float a[8];
#pragma unroll
        for (int i = 0; i < 8; i++) a[i] = ap[i * 64 + cc];
#pragma unroll
        for (int i = 0; i < 8; i++) {
            acc[i][0] = fmaf(a[i], b.x, acc[i][0]);
            acc[i][1] = fmaf(a[i], b.y, acc[i][1]);
            acc[i][2] = fmaf(a[i], b.z, acc[i][2]);
            acc[i][3] = fmaf(a[i], b.w, acc[i][3]);
        }
    }
    float4 bias = __ldg((const float4*)(vp_b + j0));
#pragma unroll
    for (int i = 0; i < 8; i++) {
        *(float4*)&g_value[(row0 + r0 + i) * 64 + j0] =
            make_float4(acc[i][0] + bias.x, acc[i][1] + bias.y,
                        acc[i][2] + bias.z, acc[i][3] + bias.w);
    }
}

// ---------------------------------------------------------------------------
// K2: depthwise 3x3 conv (sliding window) + om GEMM (64->54).
// Block = 64 consecutive pixels of one image row. 256 threads.
// ---------------------------------------------------------------------------
__global__ void __launch_bounds__(256) k2_dwom(const float* __restrict__ x,
                                               const float* __restrict__ dw_w,
                                               const float* __restrict__ dw_b,
                                               const float* __restrict__ om_w,
                                               const float* __restrict__ om_b) {
    __shared__ float dws[64][65];    // conv output [pixel][c]
    __shared__ float Wom[64 * 64];   // Wom[c*64 + j], cols 54..63 zero
    __shared__ float ob[64];
    int t = threadIdx.x;
    for (int i = t; i < 4096; i += 256) {
        int c = i >> 6, j = i & 63;
        Wom[c * 64 + j] = (j < 54) ? om_w[j * 64 + c] : 0.f;
    }
    if (t < 64) ob[t] = (t < 54) ? om_b[t] : 0.f;

    int bb = blockIdx.x >> 8;
    int p0 = (blockIdx.x & 255) * 64;
    int h = p0 >> 7;
    int w0 = p0 & 127;
    const float* xb = x + (size_t)bb * (PB * 64);

    // Phase A: conv. thread = (channel c, pixel group pg of 16), sliding window.
    {
        int c = t & 63;
        int pg = t >> 6;
        float wk[9];
#pragma unroll
        for (int k = 0; k < 9; k++) wk[k] = dw_w[c * 9 + k];
        float bias = dw_b[c];
        int wstart = w0 + pg * 16;
        const float* xc = xb + c;
        float v[3][3];
#pragma unroll
        for (int ky = 0; ky < 3; ky++) {
            int yy = h + ky - 1;
            bool yok = (unsigned)yy < 128u;
            int xm1 = wstart - 1;
            v[ky][1] = (yok && (unsigned)xm1 < 128u)
                           ? __ldg(xc + ((size_t)((yy << 7) + xm1) << 6)) : 0.f;
            v[ky][2] = yok ? __ldg(xc + ((size_t)((yy << 7) + wstart) << 6)) : 0.f;
        }
        for (int i = 0; i < 16; i++) {
            int w = wstart + i;
            int xp1 = w + 1;
#pragma unroll
            for (int ky = 0; ky < 3; ky++) {
                int yy = h + ky - 1;
                v[ky][0] = v[ky][1];
                v[ky][1] = v[ky][2];
                v[ky][2] = ((unsigned)yy < 128u && (unsigned)xp1 < 128u)
                               ? __ldg(xc + ((size_t)((yy << 7) + xp1) << 6)) : 0.f;
            }
            float acc = bias;
#pragma unroll
            for (int ky = 0; ky < 3; ky++)
#pragma unroll
                for (int kx = 0; kx < 3; kx++)
                    acc = fmaf(v[ky][kx], wk[ky * 3 + kx], acc);
            dws[pg * 16 + i][c] = acc;
        }
    }
    __syncthreads();

    // Phase B: om GEMM. thread = 4 px x 4 j (j<54 guarded).
    {
        int px0 = (t >> 4) * 4;
        int j0 = (t & 15) * 4;
        float acc[4][4] = {};
        const float* wp = Wom + j0;
#pragma unroll 4
        for (int c = 0; c < 64; c++) {
            float4 b = *(const float4*)(wp + c * 64);
#pragma unroll
            for (int i = 0; i < 4; i++) {
                float a = dws[px0 + i][c];
                acc[i][0] = fmaf(a, b.x, acc[i][0]);
                acc[i][1] = fmaf(a, b.y, acc[i][1]);
                acc[i][2] = fmaf(a, b.z, acc[i][2]);
                acc[i][3] = fmaf(a, b.w, acc[i][3]);
            }
        }
        if (j0 < 54) {
            size_t base = ((size_t)bb * PB + p0 + px0) * 54;
#pragma unroll
            for (int i = 0; i < 4; i++) {
#pragma unroll
                for (int jj = 0; jj < 4; jj++) {
                    int j = j0 + jj;
                    if (j < 54) g_om[base + (size_t)i * 54 + j] = acc[i][jj] + ob[j];
                }
            }
        }
    }
}

// ---------------------------------------------------------------------------
// K3: DCN. Phase W precomputes per-(pixel,group,tap) a clamped base pixel and
// 4 pre-masked bilinear weights (OOB corners -> weight 0, loads always
// in-bounds). Gather phase is branch-free: LDS + 4x LDG.128 + 16 FFMA per tap.
// Then op GEMM + in-register pair fold + BN + ReLU.
// Block = 32 local pixels: p0..p0+15 and p0+8192..p0+8207 (fold pairs (i,i+16)).
// ---------------------------------------------------------------------------
__global__ void __launch_bounds__(256) k3_dcn(const float* __restrict__ op_w,
                                              const float* __restrict__ op_b,
                                              const float* __restrict__ bn_g,
                                              const float* __restrict__ bn_b,
                                              const float* __restrict__ bn_m,
                                              const float* __restrict__ bn_v,
                                              float* __restrict__ out) {
    __shared__ float Wop[64 * 64];     // Wop[c*64 + j]
    __shared__ float cs[32][68];       // core output [pl][c]
    __shared__ int    s_base[576];     // (pl,g,k) -> clamped base pixel lin
    __shared__ float4 s_w[576];        // (pl,g,k) -> 4 corner weights
    __shared__ float  opb[64];
    int t = threadIdx.x;
    for (int i = t; i < 4096; i += 256) Wop[(i & 63) * 64 + (i >> 6)] = op_w[i];
    if (t < 64) opb[t] = op_b[t];

    int bb = blockIdx.x >> 9;
    int p0 = (blockIdx.x & 511) * 16;       // in [0, 8192)

    // Phase W: 32 px x 2 g x 9 k = 576 items
    for (int it = t; it < 576; it += 256) {
        int pl = it / 18;
        int rem = it - pl * 18;
        int g = rem / 9;
        int k = rem - g * 9;
        int p = p0 + ((pl < 16) ? pl : (pl - 16 + 8192));
        int h = p >> 7, w = p & 127;
        const float* om = g_om + ((size_t)bb * PB + p) * 54 + g * 27;
        float ox = om[2 * k], oy = om[2 * k + 1], m = om[18 + k];
        float ix = (float)w + ((float)(k - (k / 3) * 3) - 1.0f + ox) * 2.0f;
        float iy = (float)h + ((float)(k / 3) - 1.0f + oy) * 2.0f;
        float xf = floorf(ix), yf = floorf(iy);
        float tx = ix - xf, ty = iy - yf;
        int x0 = (int)xf, y0 = (int)yf;
        float wx0 = ((unsigned)x0 < 128u) ? (1.f - tx) : 0.f;
        float wx1 = ((unsigned)(x0 + 1) < 128u) ? tx : 0.f;
        int x0c = x0;
        if (x0 < 0)        { wx0 = wx1; wx1 = 0.f; x0c = 0; }
        else if (x0 > 126) { wx1 = wx0; wx0 = 0.f; x0c = 126; }
        float wy0 = ((unsigned)y0 < 128u) ? (1.f - ty) : 0.f;
        float wy1 = ((unsigned)(y0 + 1) < 128u) ? ty : 0.f;
        int y0c = y0;
        if (y0 < 0)        { wy0 = wy1; wy1 = 0.f; y0c = 0; }
        else if (y0 > 126) { wy1 = wy0; wy0 = 0.f; y0c = 126; }
        s_base[it] = (y0c << 7) + x0c;
        s_w[it] = make_float4(wy0 * wx0 * m, wy0 * wx1 * m,
                              wy1 * wx0 * m, wy1 * wx1 * m);
    }
    __syncthreads();

    // Gather: 16 lanes per pixel (4 channels each), 2 passes over 32 px.
    {
        int sub = t & 15;
        int g = sub >> 3;
        int d0 = (sub & 7) * 4;
        int plh = t >> 4;
        int cb = g * 32 + d0;
        const float* vb = g_value + (size_t)bb * (PB * 64) + cb;
#pragma unroll
        for (int pass = 0; pass < 2; pass++) {
            int pl = plh + pass * 16;
            int ib = pl * 18 + g * 9;
            float a0 = 0.f, a1 = 0.f, a2 = 0.f, a3 = 0.f;
#pragma unroll
            for (int k = 0; k < 9; k++) {
                int lin = s_base[ib + k];
                float4 w4 = s_w[ib + k];
                const float* q = vb + (size_t)lin * 64;
                float4 v00 = __ldg((const float4*)(q));
                float4 v01 = __ldg((const float4*)(q + 64));
                float4 v10 = __ldg((const float4*)(q + 8192));
                float4 v11 = __ldg((const float4*)(q + 8192 + 64));
                a0 = fmaf(w4.x, v00.x, a0); a1 = fmaf(w4.x, v00.y, a1);
                a2 = fmaf(w4.x, v00.z, a2); a3 = fmaf(w4.x, v00.w, a3);
                a0 = fmaf(w4.y, v01.x, a0); a1 = fmaf(w4.y, v01.y, a1);
                a2 = fmaf(w4.y, v01.z, a2); a3 = fmaf(w4.y, v01.w, a3);
                a0 = fmaf(w4.z, v10.x, a0); a1 = fmaf(w4.z, v10.y, a1);
                a2 = fmaf(w4.z, v10.z, a2); a3 = fmaf(w4.z, v10.w, a3);
                a0 = fmaf(w4.w, v11.x, a0); a1 = fmaf(w4.w, v11.y, a1);
                a2 = fmaf(w4.w, v11.z, a2); a3 = fmaf(w4.w, v11.w, a3);
            }
            *(float4*)&cs[pl][cb] = make_float4(a0, a1, a2, a3);
        }
    }
    __syncthreads();

    // op GEMM + fold + BN + ReLU. thread = px {px0,px0+1,px0+16,px0+17} x 4 j.
    {
        int px0 = (t >> 4) * 2;            // 0..30 even -> use &14 for pairs
        px0 = px0 & 14;                    // 0,2,..,14 duplicated: (t>>4) 0..15 -> 8 pairs x2
        // To keep all 256 threads busy: (t>>4) in [0,16): low 8 handle px0=2*(t>>4),
        // but we only have 8 pair-groups of 2 px. Use (t>>4)&7 for px pair, and
        // (t>>4)>>3 selects j half via j0 extension:
        int grp = (t >> 4);                // 0..15
        int pxp = (grp & 7) * 2;           // 0,2,..,14
        int j0 = (t & 15) * 4 + ((grp >> 3) ? 0 : 0); // j fully covered by 16 lanes
        // Each (pxp) is handled by two warha-groups; split j-range instead:
        // groups 0..7 -> j0 as is (lanes cover 64 j). groups 8..15 duplicate px.
        // Simplest correct scheme: only groups 0..7 compute 2 px-pairs each? 
        // Rework: 16 groups x 16 lanes; pair index = grp (0..15), covers all 16 pairs.
        pxp = grp;                          // pair index 0..15 -> rows pxp, pxp+16
        float accA[4] = {0.f, 0.f, 0.f, 0.f};   // row pxp
        float accB[4] = {0.f, 0.f, 0.f, 0.f};   // row pxp+16
        const float* wp = Wop + j0;
#pragma unroll 4
        for (int c = 0; c < 64; c++) {
            float4 b = *(const float4*)(wp + c * 64);
            float aA = cs[pxp][c];
            float aB = cs[pxp + 16][c];
            accA[0] = fmaf(aA, b.x, accA[0]); accA[1] = fmaf(aA, b.y, accA[1]);
            accA[2] = fmaf(aA, b.z, accA[2]); accA[3] = fmaf(aA, b.w, accA[3]);
            accB[0] = fmaf(aB, b.x, accB[0]); accB[1] = fmaf(aB, b.y, accB[1]);
            accB[2] = fmaf(aB, b.z, accB[2]); accB[3] = fmaf(aB, b.w, accB[3]);
        }
        int p = p0 + pxp;                  // global p in [0,8192)
        int cz = p >> 8;
        float sA = __ldg(bn_g + cz) * rsqrtf(__ldg(bn_v + cz) + 1e-5f);
        float sB = fmaf(-sA, __ldg(bn_m + cz), __ldg(bn_b + cz));
        float4 bj = *(const float4*)&opb[j0];
        float z0 = fmaf(0.5f * (accA[0] + accB[0]) + bj.x, sA, sB);
        float z1 = fmaf(0.5f * (accA[1] + accB[1]) + bj.y, sA, sB);
        float z2 = fmaf(0.5f * (accA[2] + accB[2]) + bj.z, sA, sB);
        float z3 = fmaf(0.5f * (accA[3] + accB[3]) + bj.w, sA, sB);
        int hh = (p >> 1) & 127;
        int q = p & 1;
        size_t base = (((size_t)bb * 32 + cz) * 128 + hh) * 128 + (q << 6);
        *(float4*)&out[base + j0] =
            make_float4(fmaxf(z0, 0.f), fmaxf(z1, 0.f),
                        fmaxf(z2, 0.f), fmaxf(z3, 0.f));
    }
}

// ---------------------------------------------------------------------------
extern "C" void kernel_launch(void* const* d_in, const int* in_sizes, int n_in,
                              void* d_out, int out_size) {
    const float* x    = (const float*)d_in[0];
    const float* vp_w = (const float*)d_in[1];
    const float* vp_b = (const float*)d_in[2];
    const float* dw_w = (const float*)d_in[3];
    const float* dw_b = (const float*)d_in[4];
    const float* om_w = (const float*)d_in[5];
    const float* om_b = (const float*)d_in[6];
    const float* op_w = (const float*)d_in[7];
    const float* op_b = (const float*)d_in[8];
    const float* bn_g = (const float*)d_in[9];
    const float* bn_b = (const float*)d_in[10];
    const float* bn_m = (const float*)d_in[11];
    const float* bn_v = (const float*)d_in[12];
    float* out = (float*)d_out;

    k1_valproj<<<NROWS / 128, 256>>>(x, vp_w, vp_b);
    k2_dwom<<<NB * (PB / 64), 256>>>(x, dw_w, dw_b, om_w, om_b);
    k3_dcn<<<NB * 512, 256>>>(op_w, op_b, bn_g, bn_b, bn_m, bn_v, out);
}

// round 4
// speedup vs baseline: 1.2478x; 1.2478x over previous
#include <cuda_runtime.h>
#include <cuda_bf16.h>

// Problem constants: B=8, C=64, H=W=128, G=2, D=32, K=9, OS=2.0
#define PB 16384
#define NB 8
#define NROWS (NB * PB)

__device__ float g_value[NB * PB * 64];   // (b,p,64)
__device__ float g_om[NB * PB * 54];      // (b,p,54)

// XOR swizzle: rows stride 64 floats, swizzle k by row to decollide banks.
#define SW(r) (((r) & 7) << 2)

__device__ __forceinline__ unsigned f2tf(float f) {
    unsigned r; asm("cvt.rna.tf32.f32 %0, %1;" : "=r"(r) : "f"(f)); return r;
}
__device__ __forceinline__ void split_tf(float f, unsigned& hi, unsigned& lo) {
    hi = f2tf(f);
    lo = f2tf(f - __uint_as_float(hi));
}
__device__ __forceinline__ void mma8(float* c, unsigned a0, unsigned a1,
                                     unsigned a2, unsigned a3,
                                     unsigned b0, unsigned b1) {
    asm("mma.sync.aligned.m16n8k8.row.col.f32.tf32.tf32.f32 "
        "{%0,%1,%2,%3},{%4,%5,%6,%7},{%8,%9},{%0,%1,%2,%3};"
        : "+f"(c[0]), "+f"(c[1]), "+f"(c[2]), "+f"(c[3])
        : "r"(a0), "r"(a1), "r"(a2), "r"(a3), "r"(b0), "r"(b1));
}

// ---------------------------------------------------------------------------
// K1: value projection via 3xTF32 mma. Block = 128 rows (8 warps x m16), N=64.
// A fragments loaded directly from global x; weights hi/lo in swizzled smem.
// ---------------------------------------------------------------------------
__global__ void __launch_bounds__(256) k1_valproj(const float* __restrict__ x,
                                                  const float* __restrict__ vp_w,
                                                  const float* __restrict__ vp_b) {
    __shared__ unsigned Bh[4096], Bl[4096];   // [n][k] swizzled
    int t = threadIdx.x;
    for (int i = t; i < 4096; i += 256) {
        int n = i >> 6, k = i & 63;
        unsigned h, l; split_tf(vp_w[i], h, l);
        int idx = n * 64 + (k ^ SW(n));
        Bh[idx] = h; Bl[idx] = l;
    }
    __syncthreads();

    int w = t >> 5, lane = t & 31;
    int r = lane >> 2, q = lane & 3;
    size_t row0 = (size_t)blockIdx.x * 128 + w * 16;
    const float* ar = x + (row0 + r) * 64;

    float acc[8][4];
#pragma unroll
    for (int nt = 0; nt < 8; nt++)
#pragma unroll
        for (int i = 0; i < 4; i++) acc[nt][i] = 0.f;

#pragma unroll
    for (int kc = 0; kc < 8; kc++) {
        int k = kc * 8 + q;
        float a0f = __ldg(ar + k);
        float a1f = __ldg(ar + 512 + k);
        float a2f = __ldg(ar + k + 4);
        float a3f = __ldg(ar + 512 + k + 4);
        unsigned ah0, ah1, ah2, ah3, al0, al1, al2, al3;
        split_tf(a0f, ah0, al0); split_tf(a1f, ah1, al1);
        split_tf(a2f, ah2, al2); split_tf(a3f, ah3, al3);
#pragma unroll
        for (int nt = 0; nt < 8; nt++) {
            int n0 = nt * 8 + r;
            int base = n0 * 64, s = SW(n0);
            unsigned bh0 = Bh[base + (k ^ s)];
            unsigned bh1 = Bh[base + ((k + 4) ^ s)];
            unsigned bl0 = Bl[base + (k ^ s)];
            unsigned bl1 = Bl[base + ((k + 4) ^ s)];
            mma8(acc[nt], ah0, ah1, ah2, ah3, bh0, bh1);
            mma8(acc[nt], ah0, ah1, ah2, ah3, bl0, bl1);
            mma8(acc[nt], al0, al1, al2, al3, bh0, bh1);
        }
    }
#pragma unroll
    for (int nt = 0; nt < 8; nt++) {
        int jc = nt * 8 + 2 * q;
        float2 b2 = __ldg((const float2*)(vp_b + jc));
        *(float2*)&g_value[(row0 + r) * 64 + jc] =
            make_float2(acc[nt][0] + b2.x, acc[nt][1] + b2.y);
        *(float2*)&g_value[(row0 + r + 8) * 64 + jc] =
            make_float2(acc[nt][2] + b2.x, acc[nt][3] + b2.y);
    }
}

// ---------------------------------------------------------------------------
// K2: depthwise 3x3 conv (sliding window) + om GEMM (64->54) via 3xTF32 mma.
// Block = 64 consecutive pixels of one image row. 256 threads.
// smem: dws 16KB + Bh 16KB + Bl 16KB = 48KB exactly.
// ---------------------------------------------------------------------------
__global__ void __launch_bounds__(256) k2_dwom(const float* __restrict__ x,
                                               const float* __restrict__ dw_w,
                                               const float* __restrict__ dw_b,
                                               const float* __restrict__ om_w,
                                               const float* __restrict__ om_b) {
    __shared__ float dws[4096];       // [px][c] swizzled
    __shared__ unsigned Bh[4096], Bl[4096];  // om weights [n][k] swizzled, n>=54 zero
    int t = threadIdx.x;
    for (int i = t; i < 4096; i += 256) {
        int n = i >> 6, k = i & 63;
        float wv = (n < 54) ? om_w[n * 64 + k] : 0.f;
        unsigned h, l; split_tf(wv, h, l);
        int idx = n * 64 + (k ^ SW(n));
        Bh[idx] = h; Bl[idx] = l;
    }

    int bb = blockIdx.x >> 8;
    int p0 = (blockIdx.x & 255) * 64;
    int h = p0 >> 7;
    int w0 = p0 & 127;
    const float* xb = x + (size_t)bb * (PB * 64);

    // Phase A: conv, sliding window. thread = (channel c, pixel group pg).
    {
        int c = t & 63;
        int pg = t >> 6;
        float wk[9];
#pragma unroll
        for (int k = 0; k < 9; k++) wk[k] = dw_w[c * 9 + k];
        float bias = dw_b[c];
        int wstart = w0 + pg * 16;
        const float* xc = xb + c;
        float v[3][3];
#pragma unroll
        for (int ky = 0; ky < 3; ky++) {
            int yy = h + ky - 1;
            bool yok = (unsigned)yy < 128u;
            int xm1 = wstart - 1;
            v[ky][1] = (yok && (unsigned)xm1 < 128u)
                           ? __ldg(xc + ((size_t)((yy << 7) + xm1) << 6)) : 0.f;
            v[ky][2] = yok ? __ldg(xc + ((size_t)((yy << 7) + wstart) << 6)) : 0.f;
        }
        for (int i = 0; i < 16; i++) {
            int w = wstart + i;
            int xp1 = w + 1;
#pragma unroll
            for (int ky = 0; ky < 3; ky++) {
                int yy = h + ky - 1;
                v[ky][0] = v[ky][1];
                v[ky][1] = v[ky][2];
                v[ky][2] = ((unsigned)yy < 128u && (unsigned)xp1 < 128u)
                               ? __ldg(xc + ((size_t)((yy << 7) + xp1) << 6)) : 0.f;
            }
            float acc = bias;
#pragma unroll
            for (int ky = 0; ky < 3; ky++)
#pragma unroll
                for (int kx = 0; kx < 3; kx++)
                    acc = fmaf(v[ky][kx], wk[ky * 3 + kx], acc);
            int px = pg * 16 + i;
            dws[px * 64 + (c ^ SW(px))] = acc;
        }
    }
    __syncthreads();

    // Phase B: om GEMM via mma. warp w -> n-tile w (w<7). 4 m-tiles of 16 px.
    int w = t >> 5;
    if (w < 7) {
        int lane = t & 31;
        int r = lane >> 2, q = lane & 3;
        float acc[4][4];
#pragma unroll
        for (int mt = 0; mt < 4; mt++)
#pragma unroll
            for (int i = 0; i < 4; i++) acc[mt][i] = 0.f;
        int n0 = w * 8 + r;
        int nbase = n0 * 64, ns = SW(n0);
#pragma unroll
        for (int kc = 0; kc < 8; kc++) {
            int k = kc * 8 + q;
            unsigned bh0 = Bh[nbase + (k ^ ns)];
            unsigned bh1 = Bh[nbase + ((k + 4) ^ ns)];
            unsigned bl0 = Bl[nbase + (k ^ ns)];
            unsigned bl1 = Bl[nbase + ((k + 4) ^ ns)];
#pragma unroll
            for (int mt = 0; mt < 4; mt++) {
                int rA = mt * 16 + r, rB = rA + 8;
                float a0f = dws[rA * 64 + (k ^ SW(rA))];
                float a1f = dws[rB * 64 + (k ^ SW(rB))];
                float a2f = dws[rA * 64 + ((k + 4) ^ SW(rA))];
                float a3f = dws[rB * 64 + ((k + 4) ^ SW(rB))];
                unsigned ah0, ah1, ah2, ah3, al0, al1, al2, al3;
                split_tf(a0f, ah0, al0); split_tf(a1f, ah1, al1);
                split_tf(a2f, ah2, al2); split_tf(a3f, ah3, al3);
                mma8(acc[mt], ah0, ah1, ah2, ah3, bh0, bh1);
                mma8(acc[mt], ah0, ah1, ah2, ah3, bl0, bl1);
                mma8(acc[mt], al0, al1, al2, al3, bh0, bh1);
            }
        }
        int jc = w * 8 + 2 * q;
        if (jc < 54) {
            float2 ob2 = __ldg((const float2*)(om_b + jc));
#pragma unroll
            for (int mt = 0; mt < 4; mt++) {
                int pxA = p0 + mt * 16 + r;
                size_t baseA = ((size_t)bb * PB + pxA) * 54;
                *(float2*)&g_om[baseA + jc] =
                    make_float2(acc[mt][0] + ob2.x, acc[mt][1] + ob2.y);
                *(float2*)&g_om[baseA + 54 * 8 + jc] =
                    make_float2(acc[mt][2] + ob2.x, acc[mt][3] + ob2.y);
            }
        }
    }
}

// ---------------------------------------------------------------------------
// K3: DCN bilinear gather + op GEMM (3xTF32 mma) + in-register pair fold +
// BN + ReLU. Block = 32 local pixels: p0..p0+15 and p0+8192..p0+8207.
// Fold pairs (i, i+16) = (m-tile0 row r, m-tile1 row r) -> same thread.
// ---------------------------------------------------------------------------
__global__ void __launch_bounds__(256) k3_dcn(const float* __restrict__ op_w,
                                              const float* __restrict__ op_b,
                                              const float* __restrict__ bn_g,
                                              const float* __restrict__ bn_b,
                                              const float* __restrict__ bn_m,
                                              const float* __restrict__ bn_v,
                                              float* __restrict__ out) {
    __shared__ unsigned Bh[4096], Bl[4096];  // op weights [n][k] swizzled
    __shared__ float cs[2048];               // core [pl][c] swizzled (32x64)
    __shared__ float oms[32][54];
    int t = threadIdx.x;
    for (int i = t; i < 4096; i += 256) {
        int n = i >> 6, k = i & 63;
        unsigned h, l; split_tf(op_w[i], h, l);
        int idx = n * 64 + (k ^ SW(n));
        Bh[idx] = h; Bl[idx] = l;
    }

    int bb = blockIdx.x >> 9;
    int p0 = (blockIdx.x & 511) * 16;       // in [0, 8192)

    for (int i = t; i < 32 * 54; i += 256) {
        int pl = i / 54;
        int j = i - pl * 54;
        int p = p0 + ((pl < 16) ? pl : (pl - 16 + 8192));
        oms[pl][j] = g_om[((size_t)bb * PB + p) * 54 + j];
    }
    __syncthreads();

    // Gather: 16 lanes per pixel (4 channels each), 2 passes over 32 px.
    {
        int sub = t & 15;
        int g = sub >> 3;
        int d0 = (sub & 7) * 4;
        int plh = t >> 4;
        int cb = g * 32 + d0;
        const float* vb = g_value + (size_t)bb * (PB * 64) + cb;
#pragma unroll
        for (int pass = 0; pass < 2; pass++) {
            int pl = plh + pass * 16;
            int p = p0 + plh + pass * 8192;
            int h = p >> 7;
            int w = p & 127;
            const float* omp = &oms[pl][g * 27];
            float a0 = 0.f, a1 = 0.f, a2 = 0.f, a3 = 0.f;
#pragma unroll
            for (int k = 0; k < 9; k++) {
                float ox = omp[2 * k], oy = omp[2 * k + 1], m = omp[18 + k];
                float ix = (float)w + ((float)(k - (k / 3) * 3) - 1.0f + ox) * 2.0f;
                float iy = (float)h + ((float)(k / 3) - 1.0f + oy) * 2.0f;
                float xf = floorf(ix), yf = floorf(iy);
                float tx = ix - xf, ty = iy - yf;
                int x0 = (int)xf, y0 = (int)yf;
                float wx0 = 1.f - tx, wy0 = 1.f - ty;
#pragma unroll
                for (int cr = 0; cr < 4; cr++) {
                    int dy = cr >> 1, dx = cr & 1;
                    int xc = x0 + dx, yc = y0 + dy;
                    if ((unsigned)xc < 128u && (unsigned)yc < 128u) {
                        float wgt = (dy ? ty : wy0) * (dx ? tx : wx0) * m;
                        float4 v = __ldg((const float4*)(vb + ((size_t)((yc << 7) + xc) << 6)));
                        a0 = fmaf(wgt, v.x, a0);
                        a1 = fmaf(wgt, v.y, a1);
                        a2 = fmaf(wgt, v.z, a2);
                        a3 = fmaf(wgt, v.w, a3);
                    }
                }
            }
            *(float4*)&cs[pl * 64 + (cb ^ SW(pl))] = make_float4(a0, a1, a2, a3);
        }
    }
    __syncthreads();

    // op GEMM via mma: warp w -> n-tile w; m-tiles rows 0-15 (A) and 16-31 (B).
    {
        int w = t >> 5, lane = t & 31;
        int r = lane >> 2, q = lane & 3;
        float accA[4] = {0.f, 0.f, 0.f, 0.f};
        float accB[4] = {0.f, 0.f, 0.f, 0.f};
        int n0 = w * 8 + r;
        int nbase = n0 * 64, ns = SW(n0);
#pragma unroll
        for (int kc = 0; kc < 8; kc++) {
            int k = kc * 8 + q;
            unsigned bh0 = Bh[nbase + (k ^ ns)];
            unsigned bh1 = Bh[nbase + ((k + 4) ^ ns)];
            unsigned bl0 = Bl[nbase + (k ^ ns)];
            unsigned bl1 = Bl[nbase + ((k + 4) ^ ns)];
            // m-tile 0: rows r, r+8
            {
                int rA = r, rB = r + 8;
                float a0f = cs[rA * 64 + (k ^ SW(rA))];
                float a1f = cs[rB * 64 + (k ^ SW(rB))];
                float a2f = cs[rA * 64 + ((k + 4) ^ SW(rA))];
                float a3f = cs[rB * 64 + ((k + 4) ^ SW(rB))];
                unsigned ah0, ah1, ah2, ah3, al0, al1, al2, al3;
                split_tf(a0f, ah0, al0); split_tf(a1f, ah1, al1);
                split_tf(a2f, ah2, al2); split_tf(a3f, ah3, al3);
                mma8(accA, ah0, ah1, ah2, ah3, bh0, bh1);
                mma8(accA, ah0, ah1, ah2, ah3, bl0, bl1);
                mma8(accA, al0, al1, al2, al3, bh0, bh1);
            }
            // m-tile 1: rows 16+r, 24+r
            {
                int rA = 16 + r, rB = 24 + r;
                float a0f = cs[rA * 64 + (k ^ SW(rA))];
                float a1f = cs[rB * 64 + (k ^ SW(rB))];
                float a2f = cs[rA * 64 + ((k + 4) ^ SW(rA))];
                float a3f = cs[rB * 64 + ((k + 4) ^ SW(rB))];
                unsigned ah0, ah1, ah2, ah3, al0, al1, al2, al3;
                split_tf(a0f, ah0, al0); split_tf(a1f, ah1, al1);
                split_tf(a2f, ah2, al2); split_tf(a3f, ah3, al3);
                mma8(accB, ah0, ah1, ah2, ah3, bh0, bh1);
                mma8(accB, ah0, ah1, ah2, ah3, bl0, bl1);
                mma8(accB, al0, al1, al2, al3, bh0, bh1);
            }
        }
        // Fold (row r of mt0 pairs with row r of mt1), BN, ReLU, store.
        int jc = w * 8 + 2 * q;
        float2 ob2 = __ldg((const float2*)(op_b + jc));
        int cz = p0 >> 8;
        float sA = __ldg(bn_g + cz) * rsqrtf(__ldg(bn_v + cz) + 1e-5f);
        float sB = fmaf(-sA, __ldg(bn_m + cz), __ldg(bn_b + cz));
#pragma unroll
        for (int half = 0; half < 2; half++) {
            int rr = r + half * 8;
            int i0 = half * 2, i1 = half * 2 + 1;
            int p = p0 + rr;
            float z0 = fmaf(0.5f * (accA[i0] + accB[i0]) + ob2.x, sA, sB);
            float z1 = fmaf(0.5f * (accA[i1] + accB[i1]) + ob2.y, sA, sB);
            int hh = (p >> 1) & 127;
            int qq = p & 1;
            size_t base = (((size_t)bb * 32 + cz) * 128 + hh) * 128 + (qq << 6);
            *(float2*)&out[base + jc] =
                make_float2(fmaxf(z0, 0.f), fmaxf(z1, 0.f));
        }
    }
}

// ---------------------------------------------------------------------------
extern "C" void kernel_launch(void* const* d_in, const int* in_sizes, int n_in,
                              void* d_out, int out_size) {
    const float* x    = (const float*)d_in[0];
    const float* vp_w = (const float*)d_in[1];
    const float* vp_b = (const float*)d_in[2];
    const float* dw_w = (const float*)d_in[3];
    const float* dw_b = (const float*)d_in[4];
    const float* om_w = (const float*)d_in[5];
    const float* om_b = (const float*)d_in[6];
    const float* op_w = (const float*)d_in[7];
    const float* op_b = (const float*)d_in[8];
    const float* bn_g = (const float*)d_in[9];
    const float* bn_b = (const float*)d_in[10];
    const float* bn_m = (const float*)d_in[11];
    const float* bn_v = (const float*)d_in[12];
    float* out = (float*)d_out;

    k1_valproj<<<NROWS / 128, 256>>>(x, vp_w, vp_b);
    k2_dwom<<<NB * (PB / 64), 256>>>(x, dw_w, dw_b, om_w, om_b);
    k3_dcn<<<NB * 512, 256>>>(op_w, op_b, bn_g, bn_b, bn_m, bn_v, out);
}